// round 1
// baseline (speedup 1.0000x reference)
#include <cuda_runtime.h>
#include <cstdint>
#include <math.h>

// Problem constants
#define BB 4
#define SS 4096
#define DD 64

// Tiling
#define QTILE 128
#define KTILE 128
#define NTHREADS 256

// SMEM strides (floats)
#define QT_STRIDE 132   // Qt[k][q], k in [0,64), q in [0,128)
#define VT_STRIDE 132   // Vt[d][c]
#define VN_STRIDE 68    // Vn[c][d]
#define PT_STRIDE 132   // Pt[kv][q] (xor-swizzled q)

#define SMEM_FLOATS (64*QT_STRIDE + 64*VT_STRIDE + 128*VN_STRIDE + 128*PT_STRIDE)
#define SMEM_BYTES (SMEM_FLOATS * 4)

// per-row softmax stats scratch (no allocations allowed -> device globals)
__device__ float g_rowm[BB * SS];
__device__ float g_rowz[BB * SS];

typedef unsigned long long ull;

__device__ __forceinline__ ull pack2(float lo, float hi) {
    ull r;
    asm("mov.b64 %0, {%1, %2};" : "=l"(r) : "f"(lo), "f"(hi));
    return r;
}
__device__ __forceinline__ void unpack2(ull v, float& lo, float& hi) {
    asm("mov.b64 {%0, %1}, %2;" : "=f"(lo), "=f"(hi) : "l"(v));
}
__device__ __forceinline__ ull ffma2(ull a, ull b, ull c) {
    ull d;
    asm("fma.rn.f32x2 %0, %1, %2, %3;" : "=l"(d) : "l"(a), "l"(b), "l"(c));
    return d;
}
__device__ __forceinline__ ull fmul2(ull a, ull b) {
    ull d;
    asm("mul.rn.f32x2 %0, %1, %2;" : "=l"(d) : "l"(a), "l"(b));
    return d;
}

// Kernel 1: per (batch, 128-q-row strip): scores (raw, to gmem), online softmax
// stats, and context accumulation (flash-style). 128 CTAs total.
__global__ void __launch_bounds__(NTHREADS, 1)
attn_main_kernel(const float* __restrict__ Q, const float* __restrict__ V,
                 float* __restrict__ ctx_out, float* __restrict__ attn_out)
{
    extern __shared__ float sm[];
    float* Qt = sm;                       // [64][QT_STRIDE]
    float* Vt = Qt + 64 * QT_STRIDE;      // [64][VT_STRIDE]
    float* Vn = Vt + 64 * VT_STRIDE;      // [128][VN_STRIDE]
    float* Pt = Vn + 128 * VN_STRIDE;     // [128][PT_STRIDE]

    const int tid = threadIdx.x;
    const int tx = tid & 15;     // kv-group / d-group
    const int ty = tid >> 4;     // q-group (owns q rows ty*8 .. ty*8+7)
    const int b  = blockIdx.y;
    const int q0 = blockIdx.x * QTILE;

    const float* Qg = Q + ((size_t)(b * SS + q0)) * DD;
    const float* Vg = V + ((size_t)b * SS) * DD;

    // ---- load Q strip transposed: Qt[k][q] ----
    #pragma unroll
    for (int r = 0; r < 8; r++) {
        int lin = tid + r * NTHREADS;          // float4 index, 0..2047
        int q  = lin >> 4;
        int k4 = (lin & 15) * 4;
        float4 v = *(const float4*)(Qg + q * DD + k4);
        Qt[(k4 + 0) * QT_STRIDE + q] = v.x;
        Qt[(k4 + 1) * QT_STRIDE + q] = v.y;
        Qt[(k4 + 2) * QT_STRIDE + q] = v.z;
        Qt[(k4 + 3) * QT_STRIDE + q] = v.w;
    }

    float m_run[8], Zr[8];
    #pragma unroll
    for (int i = 0; i < 8; i++) {
        m_run[i] = __int_as_float(0xff800000);  // -inf
        Zr[i] = 0.0f;
    }
    // context accumulator: rows paired along q: ctx2[ip] holds q rows (2ip, 2ip+1),
    // cols tx*4 + jd
    ull ctx2[4][4];
    #pragma unroll
    for (int ip = 0; ip < 4; ip++)
        #pragma unroll
        for (int jd = 0; jd < 4; jd++) ctx2[ip][jd] = 0ULL;

    const int swz = (tx & 7) << 2;  // quad swizzle for Pt writes

    for (int kc = 0; kc < SS / KTILE; kc++) {
        const int kv0 = kc * KTILE;
        __syncthreads();  // previous iter consumers of Vt/Vn/Pt are done

        // ---- load V chunk: Vn[c][d] natural + Vt[d][c] transposed ----
        #pragma unroll
        for (int r = 0; r < 8; r++) {
            int lin = tid + r * NTHREADS;
            int c  = lin >> 4;
            int d4 = (lin & 15) * 4;
            float4 v = *(const float4*)(Vg + (size_t)(kv0 + c) * DD + d4);
            *(float4*)(Vn + c * VN_STRIDE + d4) = v;
            Vt[(d4 + 0) * VT_STRIDE + c] = v.x;
            Vt[(d4 + 1) * VT_STRIDE + c] = v.y;
            Vt[(d4 + 2) * VT_STRIDE + c] = v.z;
            Vt[(d4 + 3) * VT_STRIDE + c] = v.w;
        }
        __syncthreads();

        // ---- GEMM1: S[8q x 8kv] = Q_tile @ V_tile^T  (pairs along kv) ----
        ull acc2[8][4];
        #pragma unroll
        for (int i = 0; i < 8; i++)
            #pragma unroll
            for (int jp = 0; jp < 4; jp++) acc2[i][jp] = 0ULL;

        #pragma unroll 4
        for (int k = 0; k < DD; k++) {
            const float* qrow = Qt + k * QT_STRIDE + ty * 8;
            const float* vrow = Vt + k * VT_STRIDE + tx * 8;
            float4 a0 = *(const float4*)(qrow);
            float4 a1 = *(const float4*)(qrow + 4);
            float4 b0 = *(const float4*)(vrow);
            float4 b1 = *(const float4*)(vrow + 4);
            ull bp0 = pack2(b0.x, b0.y);
            ull bp1 = pack2(b0.z, b0.w);
            ull bp2 = pack2(b1.x, b1.y);
            ull bp3 = pack2(b1.z, b1.w);
            float a[8] = {a0.x, a0.y, a0.z, a0.w, a1.x, a1.y, a1.z, a1.w};
            #pragma unroll
            for (int i = 0; i < 8; i++) {
                ull ap = pack2(a[i], a[i]);
                acc2[i][0] = ffma2(ap, bp0, acc2[i][0]);
                acc2[i][1] = ffma2(ap, bp1, acc2[i][1]);
                acc2[i][2] = ffma2(ap, bp2, acc2[i][2]);
                acc2[i][3] = ffma2(ap, bp3, acc2[i][3]);
            }
        }

        // unpack scores
        float sarr[8][8];
        #pragma unroll
        for (int i = 0; i < 8; i++)
            #pragma unroll
            for (int jp = 0; jp < 4; jp++)
                unpack2(acc2[i][jp], sarr[i][2 * jp], sarr[i][2 * jp + 1]);

        // ---- write raw scores to the attention output buffer ----
        #pragma unroll
        for (int i = 0; i < 8; i++) {
            size_t row = (size_t)(b * SS + q0 + ty * 8 + i);
            float* dst = attn_out + row * SS + kv0 + tx * 8;
            float4 w0 = make_float4(sarr[i][0], sarr[i][1], sarr[i][2], sarr[i][3]);
            float4 w1 = make_float4(sarr[i][4], sarr[i][5], sarr[i][6], sarr[i][7]);
            *(float4*)(dst)     = w0;
            *(float4*)(dst + 4) = w1;
        }

        // ---- online softmax update (per q row; group = 16 lanes same ty) ----
        float scale[8];
        #pragma unroll
        for (int i = 0; i < 8; i++) {
            float mx = sarr[i][0];
            #pragma unroll
            for (int j = 1; j < 8; j++) mx = fmaxf(mx, sarr[i][j]);
            #pragma unroll
            for (int off = 8; off > 0; off >>= 1)
                mx = fmaxf(mx, __shfl_xor_sync(0xffffffffu, mx, off));
            float mn = fmaxf(m_run[i], mx);
            scale[i] = __expf(m_run[i] - mn);   // 0 on first chunk (-inf)
            m_run[i] = mn;
            float rs = 0.0f;
            #pragma unroll
            for (int j = 0; j < 8; j++) {
                float p = __expf(sarr[i][j] - mn);
                sarr[i][j] = p;
                rs += p;
            }
            #pragma unroll
            for (int off = 8; off > 0; off >>= 1)
                rs += __shfl_xor_sync(0xffffffffu, rs, off);
            Zr[i] = Zr[i] * scale[i] + rs;
        }

        // rescale context accumulators
        #pragma unroll
        for (int ip = 0; ip < 4; ip++) {
            ull sp = pack2(scale[2 * ip], scale[2 * ip + 1]);
            #pragma unroll
            for (int jd = 0; jd < 4; jd++)
                ctx2[ip][jd] = fmul2(ctx2[ip][jd], sp);
        }

        // ---- store P tile to SMEM, kv-major with xor-quad swizzle on q ----
        #pragma unroll
        for (int j = 0; j < 8; j++) {
            int kv = tx * 8 + j;
            float* prow = Pt + kv * PT_STRIDE;
            float4 lo = make_float4(sarr[0][j], sarr[1][j], sarr[2][j], sarr[3][j]);
            float4 hi = make_float4(sarr[4][j], sarr[5][j], sarr[6][j], sarr[7][j]);
            *(float4*)(prow + ((ty * 8 + 0) ^ swz)) = lo;
            *(float4*)(prow + ((ty * 8 + 4) ^ swz)) = hi;
        }
        __syncthreads();

        // ---- GEMM2: ctx[8q x 4d] += P[128q x 128kv] @ V[128kv x 64d] ----
        #pragma unroll 4
        for (int kv = 0; kv < KTILE; kv++) {
            int sw2 = ((kv >> 3) & 7) << 2;
            const float* prow = Pt + kv * PT_STRIDE;
            float4 pa0 = *(const float4*)(prow + ((ty * 8 + 0) ^ sw2));
            float4 pa1 = *(const float4*)(prow + ((ty * 8 + 4) ^ sw2));
            float4 bv  = *(const float4*)(Vn + kv * VN_STRIDE + tx * 4);
            ull a20 = pack2(pa0.x, pa0.y);
            ull a21 = pack2(pa0.z, pa0.w);
            ull a22 = pack2(pa1.x, pa1.y);
            ull a23 = pack2(pa1.z, pa1.w);
            ull b0 = pack2(bv.x, bv.x);
            ull b1 = pack2(bv.y, bv.y);
            ull b2 = pack2(bv.z, bv.z);
            ull b3 = pack2(bv.w, bv.w);
            ctx2[0][0] = ffma2(a20, b0, ctx2[0][0]);
            ctx2[0][1] = ffma2(a20, b1, ctx2[0][1]);
            ctx2[0][2] = ffma2(a20, b2, ctx2[0][2]);
            ctx2[0][3] = ffma2(a20, b3, ctx2[0][3]);
            ctx2[1][0] = ffma2(a21, b0, ctx2[1][0]);
            ctx2[1][1] = ffma2(a21, b1, ctx2[1][1]);
            ctx2[1][2] = ffma2(a21, b2, ctx2[1][2]);
            ctx2[1][3] = ffma2(a21, b3, ctx2[1][3]);
            ctx2[2][0] = ffma2(a22, b0, ctx2[2][0]);
            ctx2[2][1] = ffma2(a22, b1, ctx2[2][1]);
            ctx2[2][2] = ffma2(a22, b2, ctx2[2][2]);
            ctx2[2][3] = ffma2(a22, b3, ctx2[2][3]);
            ctx2[3][0] = ffma2(a23, b0, ctx2[3][0]);
            ctx2[3][1] = ffma2(a23, b1, ctx2[3][1]);
            ctx2[3][2] = ffma2(a23, b2, ctx2[3][2]);
            ctx2[3][3] = ffma2(a23, b3, ctx2[3][3]);
        }
    }

    // ---- epilogue: context = acc / Z; stats to scratch ----
    float c[8][4];
    #pragma unroll
    for (int ip = 0; ip < 4; ip++)
        #pragma unroll
        for (int jd = 0; jd < 4; jd++)
            unpack2(ctx2[ip][jd], c[2 * ip][jd], c[2 * ip + 1][jd]);

    #pragma unroll
    for (int i = 0; i < 8; i++) {
        float invz = 1.0f / Zr[i];
        size_t row = (size_t)(b * SS + q0 + ty * 8 + i);
        float4 o = make_float4(c[i][0] * invz, c[i][1] * invz,
                               c[i][2] * invz, c[i][3] * invz);
        *(float4*)(ctx_out + row * DD + tx * 4) = o;
        if (tx == 0) {
            g_rowm[row] = m_run[i];
            g_rowz[row] = Zr[i];
        }
    }
}

// Kernel 2: in-place normalize raw scores -> attention weights.
// w = exp(s - m) / Z. Pure streaming, ~268MB read + 268MB write.
__global__ void __launch_bounds__(256)
attn_norm_kernel(float* __restrict__ attn)
{
    size_t i4 = (size_t)blockIdx.x * 256 + threadIdx.x;   // float4 index
    int row = (int)(i4 >> 10);                            // 1024 float4 per row
    float m = g_rowm[row];
    float r = 1.0f / g_rowz[row];
    float4* p = ((float4*)attn) + i4;
    float4 v = *p;
    v.x = __expf(v.x - m) * r;
    v.y = __expf(v.y - m) * r;
    v.z = __expf(v.z - m) * r;
    v.w = __expf(v.w - m) * r;
    *p = v;
}

extern "C" void kernel_launch(void* const* d_in, const int* in_sizes, int n_in,
                              void* d_out, int out_size)
{
    const float* Q = (const float*)d_in[0];
    const float* V = (const float*)d_in[1];
    float* out = (float*)d_out;
    float* ctx  = out;                          // [B, S, D]
    float* attn = out + (size_t)BB * SS * DD;   // [B, S, S]

    cudaFuncSetAttribute(attn_main_kernel,
                         cudaFuncAttributeMaxDynamicSharedMemorySize, SMEM_BYTES);

    dim3 grid1(SS / QTILE, BB);   // 32 x 4 = 128 CTAs
    attn_main_kernel<<<grid1, NTHREADS, SMEM_BYTES>>>(Q, V, ctx, attn);

    size_t nf4 = (size_t)BB * SS * SS / 4;      // 16,777,216
    attn_norm_kernel<<<(unsigned)(nf4 / 256), 256>>>(attn);
}

// round 3
// speedup vs baseline: 1.9166x; 1.9166x over previous
#include <cuda_runtime.h>
#include <cuda_bf16.h>
#include <cstdint>

#define BB 4
#define SS 4096
#define DD 64
#define QT 128
#define KT 128
#define NTH 256
#define NCHUNK (SS / KT)
#define VSTR 72   // bf16 elements per smem row (144B: conflict-free ldmatrix)

// per-row softmax stats scratch
__device__ float g_rowm[BB * SS];
__device__ float g_rowz[BB * SS];

#define NEGINF __int_as_float(0xff800000)

static __device__ __forceinline__ uint32_t smem_u32(const void* p) {
    uint32_t a;
    asm("{ .reg .u64 t; cvta.to.shared.u64 t, %1; cvt.u32.u64 %0, t; }" : "=r"(a) : "l"(p));
    return a;
}

// pack two floats to bf16x2: lower half = lo, upper half = hi
static __device__ __forceinline__ uint32_t pack_bf16(float lo, float hi) {
    uint32_t r;
    asm("cvt.rn.bf16x2.f32 %0, %1, %2;" : "=r"(r) : "f"(hi), "f"(lo));
    return r;
}

#define LDSM4(r, a) \
    asm volatile("ldmatrix.sync.aligned.m8n8.x4.shared.b16 {%0,%1,%2,%3}, [%4];" \
                 : "=r"((r)[0]), "=r"((r)[1]), "=r"((r)[2]), "=r"((r)[3]) : "r"(a))

#define LDSM4T(r, a) \
    asm volatile("ldmatrix.sync.aligned.m8n8.x4.trans.shared.b16 {%0,%1,%2,%3}, [%4];" \
                 : "=r"((r)[0]), "=r"((r)[1]), "=r"((r)[2]), "=r"((r)[3]) : "r"(a))

static __device__ __forceinline__ void mma16816(float* d, const uint32_t* a,
                                                uint32_t b0, uint32_t b1) {
    asm volatile(
        "mma.sync.aligned.m16n8k16.row.col.f32.bf16.bf16.f32 "
        "{%0,%1,%2,%3}, {%4,%5,%6,%7}, {%8,%9}, {%0,%1,%2,%3};"
        : "+f"(d[0]), "+f"(d[1]), "+f"(d[2]), "+f"(d[3])
        : "r"(a[0]), "r"(a[1]), "r"(a[2]), "r"(a[3]), "r"(b0), "r"(b1));
}

// Main kernel: flash-style. Writes raw scores to attn_out, context to ctx_out,
// per-row (m, Z) to device scratch. One CTA per (batch, 128-q-row strip).
__global__ void __launch_bounds__(NTH, 1)
attn_mma_kernel(const float* __restrict__ Q, const float* __restrict__ V,
                float* __restrict__ ctx_out, float* __restrict__ attn_out)
{
    __shared__ __align__(16) __nv_bfloat16 smH[QT * VSTR];
    __shared__ __align__(16) __nv_bfloat16 smL[QT * VSTR];

    const int tid  = threadIdx.x;
    const int w    = tid >> 5;
    const int lane = tid & 31;
    const int g    = lane >> 2;
    const int p    = lane & 3;
    const int b    = blockIdx.y;
    const int q0   = blockIdx.x * QT;

    const float* Qg = Q + (size_t)(b * SS + q0) * DD;
    const float* Vg = V + (size_t)b * SS * DD;

    const uint32_t sH = smem_u32(smH);
    const uint32_t sL = smem_u32(smL);

    // ---- stage Q (fp32) -> split hi/lo bf16 smem tiles ----
    #pragma unroll
    for (int r = 0; r < 8; r++) {
        int lin = tid + r * NTH;               // float4 index over 128x16
        int q  = lin >> 4;
        int d4 = (lin & 15) * 4;
        float4 v = *(const float4*)(Qg + q * DD + d4);
        uint32_t h01 = pack_bf16(v.x, v.y);
        uint32_t h23 = pack_bf16(v.z, v.w);
        float hx = __uint_as_float(h01 << 16);
        float hy = __uint_as_float(h01 & 0xffff0000u);
        float hz = __uint_as_float(h23 << 16);
        float hw = __uint_as_float(h23 & 0xffff0000u);
        uint32_t l01 = pack_bf16(v.x - hx, v.y - hy);
        uint32_t l23 = pack_bf16(v.z - hz, v.w - hw);
        *(uint2*)(smH + q * VSTR + d4) = make_uint2(h01, h23);
        *(uint2*)(smL + q * VSTR + d4) = make_uint2(l01, l23);
    }
    __syncthreads();

    // ldmatrix lane-address components
    const int rA = (lane & 7) + ((lane >> 3) & 1) * 8;   // A-pattern row add
    const int kA = (lane >> 4) * 8;                      // A-pattern col add
    const int rB = (lane & 7) + (lane >> 4) * 8;         // B-pattern (non-trans) row add
    const int kB = ((lane >> 3) & 1) * 8;                // B-pattern col add

    // ---- Q fragments (held in registers for the whole kernel) ----
    uint32_t qh[4][4], ql[4][4];
    #pragma unroll
    for (int ks = 0; ks < 4; ks++) {
        uint32_t off = (uint32_t)((w * 16 + rA) * VSTR + ks * 16 + kA) * 2;
        LDSM4(qh[ks], sH + off);
        LDSM4(ql[ks], sL + off);
    }

    float m0 = NEGINF, m1 = NEGINF, z0 = 0.0f, z1 = 0.0f;
    float cacc[8][4];
    #pragma unroll
    for (int j = 0; j < 8; j++)
        #pragma unroll
        for (int e = 0; e < 4; e++) cacc[j][e] = 0.0f;

    for (int c = 0; c < NCHUNK; c++) {
        __syncthreads();   // everyone done reading smem from prev iter (or Q frags)

        // ---- stage V chunk -> hi/lo bf16 smem tiles ----
        #pragma unroll
        for (int r = 0; r < 8; r++) {
            int lin = tid + r * NTH;
            int kv = lin >> 4;
            int d4 = (lin & 15) * 4;
            float4 v = *(const float4*)(Vg + (size_t)(c * KT + kv) * DD + d4);
            uint32_t h01 = pack_bf16(v.x, v.y);
            uint32_t h23 = pack_bf16(v.z, v.w);
            float hx = __uint_as_float(h01 << 16);
            float hy = __uint_as_float(h01 & 0xffff0000u);
            float hz = __uint_as_float(h23 << 16);
            float hw = __uint_as_float(h23 & 0xffff0000u);
            uint32_t l01 = pack_bf16(v.x - hx, v.y - hy);
            uint32_t l23 = pack_bf16(v.z - hz, v.w - hw);
            *(uint2*)(smH + kv * VSTR + d4) = make_uint2(h01, h23);
            *(uint2*)(smL + kv * VSTR + d4) = make_uint2(l01, l23);
        }
        __syncthreads();

        // ---- GEMM1: S[16 x 128] = Q @ V^T (3-combo bf16 split) ----
        float sacc[16][4];
        #pragma unroll
        for (int j = 0; j < 16; j++)
            #pragma unroll
            for (int e = 0; e < 4; e++) sacc[j][e] = 0.0f;

        #pragma unroll
        for (int ks = 0; ks < 4; ks++) {
            #pragma unroll
            for (int np = 0; np < 8; np++) {
                uint32_t off = (uint32_t)((np * 16 + rB) * VSTR + ks * 16 + kB) * 2;
                uint32_t bh[4], bl[4];
                LDSM4(bh, sH + off);
                LDSM4(bl, sL + off);
                mma16816(sacc[2 * np],     qh[ks], bh[0], bh[1]);
                mma16816(sacc[2 * np + 1], qh[ks], bh[2], bh[3]);
                mma16816(sacc[2 * np],     qh[ks], bl[0], bl[1]);
                mma16816(sacc[2 * np + 1], qh[ks], bl[2], bl[3]);
                mma16816(sacc[2 * np],     ql[ks], bh[0], bh[1]);
                mma16816(sacc[2 * np + 1], ql[ks], bh[2], bh[3]);
            }
        }

        // ---- write raw scores (normalized later by norm kernel) ----
        {
            float* srow0 = attn_out + (size_t)(b * SS + q0 + w * 16 + g) * SS + c * KT + 2 * p;
            float* srow1 = srow0 + (size_t)8 * SS;
            #pragma unroll
            for (int j = 0; j < 16; j++) {
                *(float2*)(srow0 + 8 * j) = make_float2(sacc[j][0], sacc[j][1]);
                *(float2*)(srow1 + 8 * j) = make_float2(sacc[j][2], sacc[j][3]);
            }
        }

        // ---- online softmax ----
        float ml0 = NEGINF, ml1 = NEGINF;
        #pragma unroll
        for (int j = 0; j < 16; j++) {
            ml0 = fmaxf(ml0, fmaxf(sacc[j][0], sacc[j][1]));
            ml1 = fmaxf(ml1, fmaxf(sacc[j][2], sacc[j][3]));
        }
        #pragma unroll
        for (int off = 1; off <= 2; off <<= 1) {
            ml0 = fmaxf(ml0, __shfl_xor_sync(0xffffffffu, ml0, off));
            ml1 = fmaxf(ml1, __shfl_xor_sync(0xffffffffu, ml1, off));
        }
        float mn0 = fmaxf(m0, ml0), mn1 = fmaxf(m1, ml1);
        float sc0 = __expf(m0 - mn0), sc1 = __expf(m1 - mn1);
        m0 = mn0; m1 = mn1;

        float s0 = 0.0f, s1 = 0.0f;
        #pragma unroll
        for (int j = 0; j < 16; j++) {
            sacc[j][0] = __expf(sacc[j][0] - mn0);
            sacc[j][1] = __expf(sacc[j][1] - mn0);
            sacc[j][2] = __expf(sacc[j][2] - mn1);
            sacc[j][3] = __expf(sacc[j][3] - mn1);
            s0 += sacc[j][0] + sacc[j][1];
            s1 += sacc[j][2] + sacc[j][3];
        }
        #pragma unroll
        for (int off = 1; off <= 2; off <<= 1) {
            s0 += __shfl_xor_sync(0xffffffffu, s0, off);
            s1 += __shfl_xor_sync(0xffffffffu, s1, off);
        }
        z0 = z0 * sc0 + s0;
        z1 = z1 * sc1 + s1;

        #pragma unroll
        for (int j = 0; j < 8; j++) {
            cacc[j][0] *= sc0; cacc[j][1] *= sc0;
            cacc[j][2] *= sc1; cacc[j][3] *= sc1;
        }

        // ---- GEMM2: ctx += P @ V (P frags straight from registers) ----
        #pragma unroll
        for (int kk = 0; kk < 8; kk++) {
            uint32_t ah[4], al[4];
            {
                float x0 = sacc[2 * kk][0],     x1 = sacc[2 * kk][1];
                float x2 = sacc[2 * kk][2],     x3 = sacc[2 * kk][3];
                float y0 = sacc[2 * kk + 1][0], y1 = sacc[2 * kk + 1][1];
                float y2 = sacc[2 * kk + 1][2], y3 = sacc[2 * kk + 1][3];
                ah[0] = pack_bf16(x0, x1);
                ah[1] = pack_bf16(x2, x3);
                ah[2] = pack_bf16(y0, y1);
                ah[3] = pack_bf16(y2, y3);
                al[0] = pack_bf16(x0 - __uint_as_float(ah[0] << 16),
                                  x1 - __uint_as_float(ah[0] & 0xffff0000u));
                al[1] = pack_bf16(x2 - __uint_as_float(ah[1] << 16),
                                  x3 - __uint_as_float(ah[1] & 0xffff0000u));
                al[2] = pack_bf16(y0 - __uint_as_float(ah[2] << 16),
                                  y1 - __uint_as_float(ah[2] & 0xffff0000u));
                al[3] = pack_bf16(y2 - __uint_as_float(ah[3] << 16),
                                  y3 - __uint_as_float(ah[3] & 0xffff0000u));
            }
            #pragma unroll
            for (int np = 0; np < 4; np++) {
                uint32_t off = (uint32_t)((kk * 16 + rA) * VSTR + np * 16 + kA) * 2;
                uint32_t bh[4], bl[4];
                LDSM4T(bh, sH + off);
                LDSM4T(bl, sL + off);
                mma16816(cacc[2 * np],     ah, bh[0], bh[1]);
                mma16816(cacc[2 * np + 1], ah, bh[2], bh[3]);
                mma16816(cacc[2 * np],     ah, bl[0], bl[1]);
                mma16816(cacc[2 * np + 1], ah, bl[2], bl[3]);
                mma16816(cacc[2 * np],     al, bh[0], bh[1]);
                mma16816(cacc[2 * np + 1], al, bh[2], bh[3]);
            }
        }
    }

    // ---- epilogue: ctx /= Z, write; stats to scratch ----
    const float iz0 = 1.0f / z0, iz1 = 1.0f / z1;
    {
        float* crow0 = ctx_out + (size_t)(b * SS + q0 + w * 16 + g) * DD + 2 * p;
        float* crow1 = crow0 + (size_t)8 * DD;
        #pragma unroll
        for (int j = 0; j < 8; j++) {
            *(float2*)(crow0 + 8 * j) = make_float2(cacc[j][0] * iz0, cacc[j][1] * iz0);
            *(float2*)(crow1 + 8 * j) = make_float2(cacc[j][2] * iz1, cacc[j][3] * iz1);
        }
    }
    if (p == 0) {
        int row = b * SS + q0 + w * 16 + g;
        g_rowm[row]     = m0;
        g_rowz[row]     = z0;
        g_rowm[row + 8] = m1;
        g_rowz[row + 8] = z1;
    }
}

// Norm kernel: w = exp(s - m) / Z, in place over the attn buffer.
__global__ void __launch_bounds__(256)
attn_norm_kernel(float* __restrict__ attn)
{
    size_t i4 = (size_t)blockIdx.x * 256 + threadIdx.x;   // float4 index
    int row = (int)(i4 >> 10);                            // 1024 float4 per row
    float m = g_rowm[row];
    float r = 1.0f / g_rowz[row];
    float4* ptr = ((float4*)attn) + i4;
    float4 v = *ptr;
    v.x = __expf(v.x - m) * r;
    v.y = __expf(v.y - m) * r;
    v.z = __expf(v.z - m) * r;
    v.w = __expf(v.w - m) * r;
    *ptr = v;
}

extern "C" void kernel_launch(void* const* d_in, const int* in_sizes, int n_in,
                              void* d_out, int out_size)
{
    const float* Q = (const float*)d_in[0];
    const float* V = (const float*)d_in[1];
    float* out  = (float*)d_out;
    float* ctx  = out;                           // [B, S, D]
    float* attn = out + (size_t)BB * SS * DD;    // [B, S, S]

    dim3 grid(SS / QT, BB);   // 32 x 4 = 128 CTAs
    attn_mma_kernel<<<grid, NTH>>>(Q, V, ctx, attn);

    size_t nf4 = (size_t)BB * SS * SS / 4;
    attn_norm_kernel<<<(unsigned)(nf4 / 256), 256>>>(attn);
}

// round 4
// speedup vs baseline: 2.2708x; 1.1848x over previous
#include <cuda_runtime.h>
#include <cuda_bf16.h>
#include <cstdint>

#define BB 4
#define SS 4096
#define DD 64
#define QT 128
#define KT 128
#define NTH 256
#define NCHUNK (SS / KT)
#define VSTR 72   // bf16 elements per smem row (144B: conflict-free ldmatrix)

#define TILE_BYTES (QT * VSTR * 2)          // 18432 bytes per tile
#define BUF_BYTES  (2 * TILE_BYTES)         // H + L
#define SMEM_TOTAL (2 * BUF_BYTES)          // double buffered = 73728

// per-row softmax stats scratch
__device__ float g_rowm[BB * SS];
__device__ float g_rowz[BB * SS];

#define NEGINF __int_as_float(0xff800000)

static __device__ __forceinline__ uint32_t smem_u32(const void* p) {
    uint32_t a;
    asm("{ .reg .u64 t; cvta.to.shared.u64 t, %1; cvt.u32.u64 %0, t; }" : "=r"(a) : "l"(p));
    return a;
}

// pack two floats to bf16x2: lower half = lo, upper half = hi
static __device__ __forceinline__ uint32_t pack_bf16(float lo, float hi) {
    uint32_t r;
    asm("cvt.rn.bf16x2.f32 %0, %1, %2;" : "=r"(r) : "f"(hi), "f"(lo));
    return r;
}

#define LDSM4(r, a) \
    asm volatile("ldmatrix.sync.aligned.m8n8.x4.shared.b16 {%0,%1,%2,%3}, [%4];" \
                 : "=r"((r)[0]), "=r"((r)[1]), "=r"((r)[2]), "=r"((r)[3]) : "r"(a))

#define LDSM4T(r, a) \
    asm volatile("ldmatrix.sync.aligned.m8n8.x4.trans.shared.b16 {%0,%1,%2,%3}, [%4];" \
                 : "=r"((r)[0]), "=r"((r)[1]), "=r"((r)[2]), "=r"((r)[3]) : "r"(a))

static __device__ __forceinline__ void mma16816(float* d, const uint32_t* a,
                                                uint32_t b0, uint32_t b1) {
    asm volatile(
        "mma.sync.aligned.m16n8k16.row.col.f32.bf16.bf16.f32 "
        "{%0,%1,%2,%3}, {%4,%5,%6,%7}, {%8,%9}, {%0,%1,%2,%3};"
        : "+f"(d[0]), "+f"(d[1]), "+f"(d[2]), "+f"(d[3])
        : "r"(a[0]), "r"(a[1]), "r"(a[2]), "r"(a[3]), "r"(b0), "r"(b1));
}

// split fp32x4 -> hi/lo bf16x2 pairs and store to the H/L tiles
static __device__ __forceinline__ void split_store(char* smbase, uint32_t off,
                                                   float4 v) {
    uint32_t h01 = pack_bf16(v.x, v.y);
    uint32_t h23 = pack_bf16(v.z, v.w);
    float hx = __uint_as_float(h01 << 16);
    float hy = __uint_as_float(h01 & 0xffff0000u);
    float hz = __uint_as_float(h23 << 16);
    float hw = __uint_as_float(h23 & 0xffff0000u);
    uint32_t l01 = pack_bf16(v.x - hx, v.y - hy);
    uint32_t l23 = pack_bf16(v.z - hz, v.w - hw);
    *(uint2*)(smbase + off)              = make_uint2(h01, h23);   // H tile
    *(uint2*)(smbase + off + TILE_BYTES) = make_uint2(l01, l23);   // L tile
}

// Main kernel: flash-style. Raw scores -> attn_out, context -> ctx_out,
// per-row (m, Z) -> device scratch. One CTA per (batch, 128-q-row strip).
__global__ void __launch_bounds__(NTH, 1)
attn_mma_kernel(const float* __restrict__ Q, const float* __restrict__ V,
                float* __restrict__ ctx_out, float* __restrict__ attn_out)
{
    extern __shared__ __align__(16) char smraw[];   // [buf0 H|L][buf1 H|L]

    const int tid  = threadIdx.x;
    const int w    = tid >> 5;
    const int lane = tid & 31;
    const int g    = lane >> 2;
    const int p    = lane & 3;
    const int b    = blockIdx.y;
    const int q0   = blockIdx.x * QT;

    const float* Qg = Q + (size_t)(b * SS + q0) * DD;
    const float* Vg = V + (size_t)b * SS * DD;

    const uint32_t sbase = smem_u32(smraw);

    // per-thread staging coordinates (128 rows x 16 float4)
    const int ldq  = tid >> 4;            // row
    const int ldd4 = (tid & 15) * 4;      // d offset
    const uint32_t stoff = (uint32_t)(ldq * VSTR + ldd4) * 2;

    // ---- stage Q -> buf0 hi/lo ----
    #pragma unroll
    for (int r = 0; r < 8; r++) {
        int lin = tid + r * NTH;
        int q  = lin >> 4;
        int d4 = (lin & 15) * 4;
        float4 v = *(const float4*)(Qg + q * DD + d4);
        split_store(smraw, (uint32_t)(q * VSTR + d4) * 2, v);
    }
    __syncthreads();

    // ldmatrix lane-address components
    const int rA = (lane & 7) + ((lane >> 3) & 1) * 8;
    const int kA = (lane >> 4) * 8;
    const int rB = (lane & 7) + (lane >> 4) * 8;
    const int kB = ((lane >> 3) & 1) * 8;

    // ---- Q fragments (registers, whole kernel) ----
    uint32_t qh[4][4], ql[4][4];
    #pragma unroll
    for (int ks = 0; ks < 4; ks++) {
        uint32_t off = (uint32_t)((w * 16 + rA) * VSTR + ks * 16 + kA) * 2;
        LDSM4(qh[ks], sbase + off);
        LDSM4(ql[ks], sbase + off + TILE_BYTES);
    }
    __syncthreads();   // frags extracted; buf0 free for chunk 0

    float m0 = NEGINF, m1 = NEGINF, z0 = 0.0f, z1 = 0.0f;
    float cacc[8][4];
    #pragma unroll
    for (int j = 0; j < 8; j++)
        #pragma unroll
        for (int e = 0; e < 4; e++) cacc[j][e] = 0.0f;

    // prefetch chunk 0 V into registers
    float4 pv[8];
    #pragma unroll
    for (int r = 0; r < 8; r++)
        pv[r] = *(const float4*)(Vg + (size_t)((r * 16 + ldq)) * DD + ldd4);

    for (int c = 0; c < NCHUNK; c++) {
        char*    smb = smraw + (c & 1) * BUF_BYTES;
        uint32_t sb  = sbase + (c & 1) * BUF_BYTES;

        // ---- convert prefetched V -> smem hi/lo ----
        #pragma unroll
        for (int r = 0; r < 8; r++)
            split_store(smb, stoff + (uint32_t)(r * 16 * VSTR) * 2, pv[r]);
        __syncthreads();

        // ---- issue prefetch for next chunk (latency hidden by MMAs) ----
        if (c + 1 < NCHUNK) {
            const float* vn = Vg + (size_t)((c + 1) * KT + ldq) * DD + ldd4;
            #pragma unroll
            for (int r = 0; r < 8; r++)
                pv[r] = *(const float4*)(vn + (size_t)(r * 16) * DD);
        }

        // ---- GEMM1: S[16 x 128] = Q @ V^T (3-combo bf16 split) ----
        float sacc[16][4];
        #pragma unroll
        for (int j = 0; j < 16; j++)
            #pragma unroll
            for (int e = 0; e < 4; e++) sacc[j][e] = 0.0f;

        #pragma unroll
        for (int ks = 0; ks < 4; ks++) {
            #pragma unroll
            for (int np = 0; np < 8; np++) {
                uint32_t off = (uint32_t)((np * 16 + rB) * VSTR + ks * 16 + kB) * 2;
                uint32_t bh[4], bl[4];
                LDSM4(bh, sb + off);
                LDSM4(bl, sb + off + TILE_BYTES);
                mma16816(sacc[2 * np],     qh[ks], bh[0], bh[1]);
                mma16816(sacc[2 * np + 1], qh[ks], bh[2], bh[3]);
                mma16816(sacc[2 * np],     qh[ks], bl[0], bl[1]);
                mma16816(sacc[2 * np + 1], qh[ks], bl[2], bl[3]);
                mma16816(sacc[2 * np],     ql[ks], bh[0], bh[1]);
                mma16816(sacc[2 * np + 1], ql[ks], bh[2], bh[3]);
            }
        }

        // ---- write raw scores ----
        {
            float* srow0 = attn_out + (size_t)(b * SS + q0 + w * 16 + g) * SS + c * KT + 2 * p;
            float* srow1 = srow0 + (size_t)8 * SS;
            #pragma unroll
            for (int j = 0; j < 16; j++) {
                *(float2*)(srow0 + 8 * j) = make_float2(sacc[j][0], sacc[j][1]);
                *(float2*)(srow1 + 8 * j) = make_float2(sacc[j][2], sacc[j][3]);
            }
        }

        // ---- online softmax ----
        float ml0 = NEGINF, ml1 = NEGINF;
        #pragma unroll
        for (int j = 0; j < 16; j++) {
            ml0 = fmaxf(ml0, fmaxf(sacc[j][0], sacc[j][1]));
            ml1 = fmaxf(ml1, fmaxf(sacc[j][2], sacc[j][3]));
        }
        #pragma unroll
        for (int off = 1; off <= 2; off <<= 1) {
            ml0 = fmaxf(ml0, __shfl_xor_sync(0xffffffffu, ml0, off));
            ml1 = fmaxf(ml1, __shfl_xor_sync(0xffffffffu, ml1, off));
        }
        float mn0 = fmaxf(m0, ml0), mn1 = fmaxf(m1, ml1);
        float sc0 = __expf(m0 - mn0), sc1 = __expf(m1 - mn1);
        m0 = mn0; m1 = mn1;

        float s0 = 0.0f, s1 = 0.0f;
        #pragma unroll
        for (int j = 0; j < 16; j++) {
            sacc[j][0] = __expf(sacc[j][0] - mn0);
            sacc[j][1] = __expf(sacc[j][1] - mn0);
            sacc[j][2] = __expf(sacc[j][2] - mn1);
            sacc[j][3] = __expf(sacc[j][3] - mn1);
            s0 += sacc[j][0] + sacc[j][1];
            s1 += sacc[j][2] + sacc[j][3];
        }
        #pragma unroll
        for (int off = 1; off <= 2; off <<= 1) {
            s0 += __shfl_xor_sync(0xffffffffu, s0, off);
            s1 += __shfl_xor_sync(0xffffffffu, s1, off);
        }
        z0 = z0 * sc0 + s0;
        z1 = z1 * sc1 + s1;

        #pragma unroll
        for (int j = 0; j < 8; j++) {
            cacc[j][0] *= sc0; cacc[j][1] *= sc0;
            cacc[j][2] *= sc1; cacc[j][3] *= sc1;
        }

        // ---- GEMM2: ctx += P(bf16) @ (Vh + Vl)  [2-combo] ----
        #pragma unroll
        for (int kk = 0; kk < 8; kk++) {
            uint32_t ah[4];
            ah[0] = pack_bf16(sacc[2 * kk][0],     sacc[2 * kk][1]);
            ah[1] = pack_bf16(sacc[2 * kk][2],     sacc[2 * kk][3]);
            ah[2] = pack_bf16(sacc[2 * kk + 1][0], sacc[2 * kk + 1][1]);
            ah[3] = pack_bf16(sacc[2 * kk + 1][2], sacc[2 * kk + 1][3]);
            #pragma unroll
            for (int np = 0; np < 4; np++) {
                uint32_t off = (uint32_t)((kk * 16 + rA) * VSTR + np * 16 + kA) * 2;
                uint32_t bh[4], bl[4];
                LDSM4T(bh, sb + off);
                LDSM4T(bl, sb + off + TILE_BYTES);
                mma16816(cacc[2 * np],     ah, bh[0], bh[1]);
                mma16816(cacc[2 * np + 1], ah, bh[2], bh[3]);
                mma16816(cacc[2 * np],     ah, bl[0], bl[1]);
                mma16816(cacc[2 * np + 1], ah, bl[2], bl[3]);
            }
        }
    }

    // ---- epilogue ----
    const float iz0 = 1.0f / z0, iz1 = 1.0f / z1;
    {
        float* crow0 = ctx_out + (size_t)(b * SS + q0 + w * 16 + g) * DD + 2 * p;
        float* crow1 = crow0 + (size_t)8 * DD;
        #pragma unroll
        for (int j = 0; j < 8; j++) {
            *(float2*)(crow0 + 8 * j) = make_float2(cacc[j][0] * iz0, cacc[j][1] * iz0);
            *(float2*)(crow1 + 8 * j) = make_float2(cacc[j][2] * iz1, cacc[j][3] * iz1);
        }
    }
    if (p == 0) {
        int row = b * SS + q0 + w * 16 + g;
        g_rowm[row]     = m0;
        g_rowz[row]     = z0;
        g_rowm[row + 8] = m1;
        g_rowz[row + 8] = z1;
    }
}

// Norm kernel: w = exp(s - m) / Z, in place over the attn buffer.
__global__ void __launch_bounds__(256)
attn_norm_kernel(float* __restrict__ attn)
{
    size_t i4 = (size_t)blockIdx.x * 256 + threadIdx.x;   // float4 index
    int row = (int)(i4 >> 10);                            // 1024 float4 per row
    float m = g_rowm[row];
    float r = 1.0f / g_rowz[row];
    float4* ptr = ((float4*)attn) + i4;
    float4 v = *ptr;
    v.x = __expf(v.x - m) * r;
    v.y = __expf(v.y - m) * r;
    v.z = __expf(v.z - m) * r;
    v.w = __expf(v.w - m) * r;
    *ptr = v;
}

extern "C" void kernel_launch(void* const* d_in, const int* in_sizes, int n_in,
                              void* d_out, int out_size)
{
    const float* Q = (const float*)d_in[0];
    const float* V = (const float*)d_in[1];
    float* out  = (float*)d_out;
    float* ctx  = out;                           // [B, S, D]
    float* attn = out + (size_t)BB * SS * DD;    // [B, S, S]

    cudaFuncSetAttribute(attn_mma_kernel,
                         cudaFuncAttributeMaxDynamicSharedMemorySize, SMEM_TOTAL);

    dim3 grid(SS / QT, BB);   // 32 x 4 = 128 CTAs
    attn_mma_kernel<<<grid, NTH, SMEM_TOTAL>>>(Q, V, ctx, attn);

    size_t nf4 = (size_t)BB * SS * SS / 4;
    attn_norm_kernel<<<(unsigned)(nf4 / 256), 256>>>(attn);
}

// round 5
// speedup vs baseline: 2.7782x; 1.2235x over previous
#include <cuda_runtime.h>
#include <cuda_fp16.h>
#include <cstdint>

#define BB 4
#define SS 4096
#define DD 64
#define QT 128
#define KT 128
#define NTH 256
#define NCHUNK (SS / KT)
#define VSTR 72   // fp16 elements per smem row (144B: conflict-free ldmatrix)

#define TILE_BYTES (QT * VSTR * 2)          // 18432 bytes per tile
#define BUF_BYTES  (2 * TILE_BYTES)         // H + L
#define SMEM_TOTAL (2 * BUF_BYTES)          // double buffered = 73728

// per-row softmax stats scratch
__device__ float g_rowm[BB * SS];
__device__ float g_rowz[BB * SS];

#define NEGINF __int_as_float(0xff800000)

static __device__ __forceinline__ uint32_t smem_u32(const void* p) {
    uint32_t a;
    asm("{ .reg .u64 t; cvta.to.shared.u64 t, %1; cvt.u32.u64 %0, t; }" : "=r"(a) : "l"(p));
    return a;
}

// pack two floats to f16x2: lower half = lo, upper half = hi
static __device__ __forceinline__ uint32_t pack_f16(float lo, float hi) {
    uint32_t r;
    asm("cvt.rn.f16x2.f32 %0, %1, %2;" : "=r"(r) : "f"(hi), "f"(lo));
    return r;
}

#define LDSM4(r, a) \
    asm volatile("ldmatrix.sync.aligned.m8n8.x4.shared.b16 {%0,%1,%2,%3}, [%4];" \
                 : "=r"((r)[0]), "=r"((r)[1]), "=r"((r)[2]), "=r"((r)[3]) : "r"(a))

#define LDSM4T(r, a) \
    asm volatile("ldmatrix.sync.aligned.m8n8.x4.trans.shared.b16 {%0,%1,%2,%3}, [%4];" \
                 : "=r"((r)[0]), "=r"((r)[1]), "=r"((r)[2]), "=r"((r)[3]) : "r"(a))

static __device__ __forceinline__ void mma16816(float* d, const uint32_t* a,
                                                uint32_t b0, uint32_t b1) {
    asm volatile(
        "mma.sync.aligned.m16n8k16.row.col.f32.f16.f16.f32 "
        "{%0,%1,%2,%3}, {%4,%5,%6,%7}, {%8,%9}, {%0,%1,%2,%3};"
        : "+f"(d[0]), "+f"(d[1]), "+f"(d[2]), "+f"(d[3])
        : "r"(a[0]), "r"(a[1]), "r"(a[2]), "r"(a[3]), "r"(b0), "r"(b1));
}

// split fp32x4 -> hi/lo fp16x2 pairs and store to the H/L tiles
static __device__ __forceinline__ void split_store(char* smbase, uint32_t off,
                                                   float4 v) {
    __half hx = __float2half_rn(v.x);
    __half hy = __float2half_rn(v.y);
    __half hz = __float2half_rn(v.z);
    __half hw = __float2half_rn(v.w);
    uint32_t h01 = pack_f16(__half2float(hx) * 0.0f + v.x, v.y);   // placeholder avoided below
    (void)h01;
    uint2 H, L;
    H.x = pack_f16(v.x, v.y);
    H.y = pack_f16(v.z, v.w);
    L.x = pack_f16(v.x - __half2float(hx), v.y - __half2float(hy));
    L.y = pack_f16(v.z - __half2float(hz), v.w - __half2float(hw));
    *(uint2*)(smbase + off)              = H;   // H tile
    *(uint2*)(smbase + off + TILE_BYTES) = L;   // L tile
}

// Main kernel: flash-style. Raw scores -> attn_out, context -> ctx_out,
// per-row (m, Z) -> device scratch. One CTA per (batch, 128-q-row strip).
__global__ void __launch_bounds__(NTH, 1)
attn_mma_kernel(const float* __restrict__ Q, const float* __restrict__ V,
                float* __restrict__ ctx_out, float* __restrict__ attn_out)
{
    extern __shared__ __align__(16) char smraw[];   // [buf0 H|L][buf1 H|L]

    const int tid  = threadIdx.x;
    const int w    = tid >> 5;
    const int lane = tid & 31;
    const int g    = lane >> 2;
    const int p    = lane & 3;
    const int b    = blockIdx.y;
    const int q0   = blockIdx.x * QT;

    const float* Qg = Q + (size_t)(b * SS + q0) * DD;
    const float* Vg = V + (size_t)b * SS * DD;

    const uint32_t sbase = smem_u32(smraw);

    // per-thread staging coordinates (128 rows x 16 float4)
    const int ldq  = tid >> 4;            // row
    const int ldd4 = (tid & 15) * 4;      // d offset
    const uint32_t stoff = (uint32_t)(ldq * VSTR + ldd4) * 2;

    // ---- stage Q -> buf0 hi/lo ----
    #pragma unroll
    for (int r = 0; r < 8; r++) {
        int lin = tid + r * NTH;
        int q  = lin >> 4;
        int d4 = (lin & 15) * 4;
        float4 v = *(const float4*)(Qg + q * DD + d4);
        split_store(smraw, (uint32_t)(q * VSTR + d4) * 2, v);
    }
    __syncthreads();

    // ldmatrix lane-address components
    const int rA = (lane & 7) + ((lane >> 3) & 1) * 8;
    const int kA = (lane >> 4) * 8;
    const int rB = (lane & 7) + (lane >> 4) * 8;
    const int kB = ((lane >> 3) & 1) * 8;

    // ---- Q fragments (registers, whole kernel) ----
    uint32_t qh[4][4], ql[4][4];
    #pragma unroll
    for (int ks = 0; ks < 4; ks++) {
        uint32_t off = (uint32_t)((w * 16 + rA) * VSTR + ks * 16 + kA) * 2;
        LDSM4(qh[ks], sbase + off);
        LDSM4(ql[ks], sbase + off + TILE_BYTES);
    }
    __syncthreads();   // frags extracted; buf0 free for chunk 0

    float m0 = NEGINF, m1 = NEGINF, z0 = 0.0f, z1 = 0.0f;
    float cacc[8][4];
    #pragma unroll
    for (int j = 0; j < 8; j++)
        #pragma unroll
        for (int e = 0; e < 4; e++) cacc[j][e] = 0.0f;

    // prefetch chunk 0 V into registers
    float4 pv[8];
    #pragma unroll
    for (int r = 0; r < 8; r++)
        pv[r] = *(const float4*)(Vg + (size_t)((r * 16 + ldq)) * DD + ldd4);

    for (int c = 0; c < NCHUNK; c++) {
        char*    smb = smraw + (c & 1) * BUF_BYTES;
        uint32_t sb  = sbase + (c & 1) * BUF_BYTES;

        // ---- convert prefetched V -> smem hi/lo ----
        #pragma unroll
        for (int r = 0; r < 8; r++)
            split_store(smb, stoff + (uint32_t)(r * 16 * VSTR) * 2, pv[r]);
        __syncthreads();

        // ---- issue prefetch for next chunk (latency hidden by MMAs) ----
        if (c + 1 < NCHUNK) {
            const float* vn = Vg + (size_t)((c + 1) * KT + ldq) * DD + ldd4;
            #pragma unroll
            for (int r = 0; r < 8; r++)
                pv[r] = *(const float4*)(vn + (size_t)(r * 16) * DD);
        }

        // ---- GEMM1: S[16 x 128] = Q @ V^T (3-combo fp16 split) ----
        float sacc[16][4];
        #pragma unroll
        for (int j = 0; j < 16; j++)
            #pragma unroll
            for (int e = 0; e < 4; e++) sacc[j][e] = 0.0f;

        #pragma unroll
        for (int ks = 0; ks < 4; ks++) {
            #pragma unroll
            for (int np = 0; np < 8; np++) {
                uint32_t off = (uint32_t)((np * 16 + rB) * VSTR + ks * 16 + kB) * 2;
                uint32_t bh[4], bl[4];
                LDSM4(bh, sb + off);
                LDSM4(bl, sb + off + TILE_BYTES);
                mma16816(sacc[2 * np],     qh[ks], bh[0], bh[1]);
                mma16816(sacc[2 * np + 1], qh[ks], bh[2], bh[3]);
                mma16816(sacc[2 * np],     qh[ks], bl[0], bl[1]);
                mma16816(sacc[2 * np + 1], qh[ks], bl[2], bl[3]);
                mma16816(sacc[2 * np],     ql[ks], bh[0], bh[1]);
                mma16816(sacc[2 * np + 1], ql[ks], bh[2], bh[3]);
            }
        }

        // ---- write raw scores ----
        {
            float* srow0 = attn_out + (size_t)(b * SS + q0 + w * 16 + g) * SS + c * KT + 2 * p;
            float* srow1 = srow0 + (size_t)8 * SS;
            #pragma unroll
            for (int j = 0; j < 16; j++) {
                *(float2*)(srow0 + 8 * j) = make_float2(sacc[j][0], sacc[j][1]);
                *(float2*)(srow1 + 8 * j) = make_float2(sacc[j][2], sacc[j][3]);
            }
        }

        // ---- online softmax ----
        float ml0 = NEGINF, ml1 = NEGINF;
        #pragma unroll
        for (int j = 0; j < 16; j++) {
            ml0 = fmaxf(ml0, fmaxf(sacc[j][0], sacc[j][1]));
            ml1 = fmaxf(ml1, fmaxf(sacc[j][2], sacc[j][3]));
        }
        #pragma unroll
        for (int off = 1; off <= 2; off <<= 1) {
            ml0 = fmaxf(ml0, __shfl_xor_sync(0xffffffffu, ml0, off));
            ml1 = fmaxf(ml1, __shfl_xor_sync(0xffffffffu, ml1, off));
        }
        float mn0 = fmaxf(m0, ml0), mn1 = fmaxf(m1, ml1);
        float sc0 = __expf(m0 - mn0), sc1 = __expf(m1 - mn1);
        m0 = mn0; m1 = mn1;

        float s0 = 0.0f, s1 = 0.0f;
        #pragma unroll
        for (int j = 0; j < 16; j++) {
            sacc[j][0] = __expf(sacc[j][0] - mn0);
            sacc[j][1] = __expf(sacc[j][1] - mn0);
            sacc[j][2] = __expf(sacc[j][2] - mn1);
            sacc[j][3] = __expf(sacc[j][3] - mn1);
            s0 += sacc[j][0] + sacc[j][1];
            s1 += sacc[j][2] + sacc[j][3];
        }
        #pragma unroll
        for (int off = 1; off <= 2; off <<= 1) {
            s0 += __shfl_xor_sync(0xffffffffu, s0, off);
            s1 += __shfl_xor_sync(0xffffffffu, s1, off);
        }
        z0 = z0 * sc0 + s0;
        z1 = z1 * sc1 + s1;

        #pragma unroll
        for (int j = 0; j < 8; j++) {
            cacc[j][0] *= sc0; cacc[j][1] *= sc0;
            cacc[j][2] *= sc1; cacc[j][3] *= sc1;
        }

        // ---- GEMM2: ctx += P(fp16) @ Vh  [1 combo] ----
        #pragma unroll
        for (int kk = 0; kk < 8; kk++) {
            uint32_t ah[4];
            ah[0] = pack_f16(sacc[2 * kk][0],     sacc[2 * kk][1]);
            ah[1] = pack_f16(sacc[2 * kk][2],     sacc[2 * kk][3]);
            ah[2] = pack_f16(sacc[2 * kk + 1][0], sacc[2 * kk + 1][1]);
            ah[3] = pack_f16(sacc[2 * kk + 1][2], sacc[2 * kk + 1][3]);
            #pragma unroll
            for (int np = 0; np < 4; np++) {
                uint32_t off = (uint32_t)((kk * 16 + rA) * VSTR + np * 16 + kA) * 2;
                uint32_t bh[4];
                LDSM4T(bh, sb + off);
                mma16816(cacc[2 * np],     ah, bh[0], bh[1]);
                mma16816(cacc[2 * np + 1], ah, bh[2], bh[3]);
            }
        }
    }

    // ---- epilogue ----
    const float iz0 = 1.0f / z0, iz1 = 1.0f / z1;
    {
        float* crow0 = ctx_out + (size_t)(b * SS + q0 + w * 16 + g) * DD + 2 * p;
        float* crow1 = crow0 + (size_t)8 * DD;
        #pragma unroll
        for (int j = 0; j < 8; j++) {
            *(float2*)(crow0 + 8 * j) = make_float2(cacc[j][0] * iz0, cacc[j][1] * iz0);
            *(float2*)(crow1 + 8 * j) = make_float2(cacc[j][2] * iz1, cacc[j][3] * iz1);
        }
    }
    if (p == 0) {
        int row = b * SS + q0 + w * 16 + g;
        g_rowm[row]     = m0;
        g_rowz[row]     = z0;
        g_rowm[row + 8] = m1;
        g_rowz[row + 8] = z1;
    }
}

// Norm kernel: w = exp(s - m) / Z, in place. One block per attn row.
__global__ void __launch_bounds__(512)
attn_norm_kernel(float* __restrict__ attn)
{
    const int row = blockIdx.x;
    const float m = g_rowm[row];
    const float r = 1.0f / g_rowz[row];
    float4* base = (float4*)(attn + (size_t)row * SS) + threadIdx.x;
    #pragma unroll
    for (int k = 0; k < 2; k++) {
        float4 v = __ldcs(base + k * 512);
        v.x = __expf(v.x - m) * r;
        v.y = __expf(v.y - m) * r;
        v.z = __expf(v.z - m) * r;
        v.w = __expf(v.w - m) * r;
        __stcs(base + k * 512, v);
    }
}

extern "C" void kernel_launch(void* const* d_in, const int* in_sizes, int n_in,
                              void* d_out, int out_size)
{
    const float* Q = (const float*)d_in[0];
    const float* V = (const float*)d_in[1];
    float* out  = (float*)d_out;
    float* ctx  = out;                           // [B, S, D]
    float* attn = out + (size_t)BB * SS * DD;    // [B, S, S]

    cudaFuncSetAttribute(attn_mma_kernel,
                         cudaFuncAttributeMaxDynamicSharedMemorySize, SMEM_TOTAL);

    dim3 grid(SS / QT, BB);   // 32 x 4 = 128 CTAs
    attn_mma_kernel<<<grid, NTH, SMEM_TOTAL>>>(Q, V, ctx, attn);

    attn_norm_kernel<<<BB * SS, 512>>>(attn);
}